// round 1
// baseline (speedup 1.0000x reference)
#include <cuda_runtime.h>
#include <math.h>

// Problem constants
#define BB 2
#define SS 2048
#define EE 1024
#define HH 16
#define HD 64
#define KD 64
#define VD 64
#define BH (BB*HH)
#define SCALE 0.125f   // 1/sqrt(64)

// padded stride for transposed (d-major) smem tiles: keeps 16B alignment,
// spreads rows across banks (68 % 32 = 4)
#define TS 68

// Scratch (allocation-free rule: __device__ globals)
static __device__ float g_q[(size_t)BH*SS*KD];        // (bh, s, d)
static __device__ float g_k[(size_t)BH*SS*KD];
static __device__ float g_v[(size_t)BH*SS*VD];
static __device__ float g_att[(size_t)BB*SS*EE];      // (b, s, h*VD)

// ---------------------------------------------------------------------------
// Kernel 1: per-head QKV projection.  q/k/v[bh][s][:] = x[b][s][h*64:+64] @ W + b
// Block: (b,h, 64-row s tile). 256 threads, 4x4 micro-tiles, outer-product GEMM.
// ---------------------------------------------------------------------------
__global__ __launch_bounds__(256) void qkv_kernel(
    const float* __restrict__ x,
    const float* __restrict__ Wq, const float* __restrict__ bq,
    const float* __restrict__ Wk, const float* __restrict__ bk,
    const float* __restrict__ Wv, const float* __restrict__ bv)
{
    __shared__ __align__(16) float xT[64*TS];   // [d][r]
    __shared__ __align__(16) float Ws[64*64];   // [d][k]

    int bh = blockIdx.x; int b = bh >> 4, h = bh & 15;
    int s0 = blockIdx.y * 64;
    int tid = threadIdx.x;
    int tx = tid & 15, ty = tid >> 4;

    for (int idx = tid; idx < 4096; idx += 256) {
        int r = idx >> 6, d = idx & 63;
        xT[d*TS + r] = x[((size_t)b*SS + s0 + r)*EE + h*HD + d];
    }

    const float* Wp[3] = {Wq, Wk, Wv};
    const float* bp[3] = {bq, bk, bv};
    float*       op[3] = {g_q, g_k, g_v};

    for (int w = 0; w < 3; ++w) {
        __syncthreads();
        for (int idx = tid; idx < 4096; idx += 256) Ws[idx] = Wp[w][idx];
        __syncthreads();

        float acc[4][4] = {};
        #pragma unroll 8
        for (int dd = 0; dd < 64; ++dd) {
            float4 a4 = *(const float4*)&xT[dd*TS + ty*4];
            float4 w4 = *(const float4*)&Ws[dd*64 + tx*4];
            float av[4] = {a4.x, a4.y, a4.z, a4.w};
            float wv[4] = {w4.x, w4.y, w4.z, w4.w};
            #pragma unroll
            for (int i = 0; i < 4; ++i)
                #pragma unroll
                for (int j = 0; j < 4; ++j)
                    acc[i][j] += av[i] * wv[j];
        }

        float bias[4];
        #pragma unroll
        for (int j = 0; j < 4; ++j) bias[j] = bp[w][tx*4 + j];

        float* out = op[w];
        #pragma unroll
        for (int i = 0; i < 4; ++i)
            #pragma unroll
            for (int j = 0; j < 4; ++j)
                out[((size_t)bh*SS + s0 + ty*4 + i)*64 + tx*4 + j] = acc[i][j] + bias[j];
    }
}

// ---------------------------------------------------------------------------
// Kernel 2: flash attention per (b,h, 64-row q tile), streaming 64-wide kv tiles.
// Online softmax; logits = (q.k)*SCALE*mask.
// ---------------------------------------------------------------------------
#define ATTN_SMEM ((3*64*TS + 2*64*64)*4)   // 84992 bytes

__global__ __launch_bounds__(256) void attn_kernel(const float* __restrict__ mask)
{
    extern __shared__ float sm[];
    float* qT = sm;                 // [d][r] stride TS
    float* kT = sm + 64*TS;         // [d][s] stride TS
    float* Pt = sm + 2*64*TS;       // [s][r] stride TS
    float* Vs = sm + 3*64*TS;       // [s][c] stride 64
    float* Ms = Vs + 64*64;         // [r][c] stride 64

    int bh = blockIdx.x; int b = bh >> 4, h = bh & 15;
    int q0 = blockIdx.y * 64;
    int tid = threadIdx.x;
    int tx = tid & 15, ty = tid >> 4;

    for (int idx = tid; idx < 4096; idx += 256) {
        int r = idx >> 6, d = idx & 63;
        qT[d*TS + r] = g_q[((size_t)bh*SS + q0 + r)*KD + d];
    }

    float m[4], l[4], acc[4][4] = {};
    #pragma unroll
    for (int i = 0; i < 4; ++i) { m[i] = -INFINITY; l[i] = 0.f; }

    for (int jt = 0; jt < SS/64; ++jt) {
        int s0 = jt * 64;
        __syncthreads();   // prev iter done with kT/Vs/Ms/Pt
        for (int idx = tid; idx < 4096; idx += 256) {
            int r = idx >> 6, d = idx & 63;
            kT[d*TS + r] = g_k[((size_t)bh*SS + s0 + r)*KD + d];
            Vs[idx]      = g_v[((size_t)bh*SS + s0 + r)*VD + d];
            Ms[idx]      = mask[(size_t)(q0 + r)*SS + s0 + d];
        }
        __syncthreads();

        // S = Q K^T  (sum over d, outer product)
        float sacc[4][4] = {};
        #pragma unroll 8
        for (int dd = 0; dd < 64; ++dd) {
            float4 a4 = *(const float4*)&qT[dd*TS + ty*4];
            float4 b4 = *(const float4*)&kT[dd*TS + tx*4];
            float av[4] = {a4.x, a4.y, a4.z, a4.w};
            float bv[4] = {b4.x, b4.y, b4.z, b4.w};
            #pragma unroll
            for (int i = 0; i < 4; ++i)
                #pragma unroll
                for (int j = 0; j < 4; ++j)
                    sacc[i][j] += av[i] * bv[j];
        }

        // logits = S * SCALE * mask
        #pragma unroll
        for (int i = 0; i < 4; ++i)
            #pragma unroll
            for (int j = 0; j < 4; ++j)
                sacc[i][j] *= SCALE * Ms[(ty*4 + i)*64 + tx*4 + j];

        // online softmax update (row reduction across the 16 tx lanes)
        #pragma unroll
        for (int i = 0; i < 4; ++i) {
            float rm = fmaxf(fmaxf(sacc[i][0], sacc[i][1]), fmaxf(sacc[i][2], sacc[i][3]));
            #pragma unroll
            for (int off = 1; off < 16; off <<= 1)
                rm = fmaxf(rm, __shfl_xor_sync(0xffffffffu, rm, off));
            float nm = fmaxf(m[i], rm);
            float corr = __expf(m[i] - nm);     // expf(-inf)=0 on first tile
            float rs = 0.f;
            #pragma unroll
            for (int j = 0; j < 4; ++j) {
                float p = __expf(sacc[i][j] - nm);
                sacc[i][j] = p;
                rs += p;
            }
            #pragma unroll
            for (int off = 1; off < 16; off <<= 1)
                rs += __shfl_xor_sync(0xffffffffu, rs, off);
            l[i] = l[i]*corr + rs;
            m[i] = nm;
            #pragma unroll
            for (int j = 0; j < 4; ++j) acc[i][j] *= corr;
        }

        // stage P transposed for the PV outer-product GEMM
        #pragma unroll
        for (int i = 0; i < 4; ++i)
            #pragma unroll
            for (int j = 0; j < 4; ++j)
                Pt[(tx*4 + j)*TS + ty*4 + i] = sacc[i][j];
        __syncthreads();

        // O += P V  (sum over s, outer product)
        #pragma unroll 8
        for (int ss = 0; ss < 64; ++ss) {
            float4 p4 = *(const float4*)&Pt[ss*TS + ty*4];
            float4 v4 = *(const float4*)&Vs[ss*64 + tx*4];
            float pv[4] = {p4.x, p4.y, p4.z, p4.w};
            float vv[4] = {v4.x, v4.y, v4.z, v4.w};
            #pragma unroll
            for (int i = 0; i < 4; ++i)
                #pragma unroll
                for (int j = 0; j < 4; ++j)
                    acc[i][j] += pv[i] * vv[j];
        }
    }

    // normalize and write (B, S, H*VD)
    #pragma unroll
    for (int i = 0; i < 4; ++i) {
        float inv = 1.f / l[i];
        #pragma unroll
        for (int j = 0; j < 4; ++j)
            g_att[((size_t)b*SS + q0 + ty*4 + i)*EE + h*VD + tx*4 + j] = acc[i][j] * inv;
    }
}

// ---------------------------------------------------------------------------
// Kernel 3: output projection  out = att (4096x1024) @ Wo (1024x1024) + bo
// ---------------------------------------------------------------------------
__global__ __launch_bounds__(256) void out_kernel(
    const float* __restrict__ Wo, const float* __restrict__ bo,
    float* __restrict__ out)
{
    __shared__ __align__(16) float At[64*TS];   // [d][r]
    __shared__ __align__(16) float Bs[64*64];   // [d][e]

    int e0 = blockIdx.x * 64;
    int r0 = blockIdx.y * 64;
    int tid = threadIdx.x;
    int tx = tid & 15, ty = tid >> 4;

    float acc[4][4] = {};
    for (int kc = 0; kc < EE; kc += 64) {
        __syncthreads();
        for (int idx = tid; idx < 4096; idx += 256) {
            int r = idx >> 6, d = idx & 63;
            At[d*TS + r] = g_att[(size_t)(r0 + r)*EE + kc + d];
            Bs[idx]      = Wo[(size_t)(kc + r)*EE + e0 + d];
        }
        __syncthreads();

        #pragma unroll 8
        for (int dd = 0; dd < 64; ++dd) {
            float4 a4 = *(const float4*)&At[dd*TS + ty*4];
            float4 w4 = *(const float4*)&Bs[dd*64 + tx*4];
            float av[4] = {a4.x, a4.y, a4.z, a4.w};
            float wv[4] = {w4.x, w4.y, w4.z, w4.w};
            #pragma unroll
            for (int i = 0; i < 4; ++i)
                #pragma unroll
                for (int j = 0; j < 4; ++j)
                    acc[i][j] += av[i] * wv[j];
        }
    }

    float bias[4];
    #pragma unroll
    for (int j = 0; j < 4; ++j) bias[j] = bo[e0 + tx*4 + j];
    #pragma unroll
    for (int i = 0; i < 4; ++i)
        #pragma unroll
        for (int j = 0; j < 4; ++j)
            out[(size_t)(r0 + ty*4 + i)*EE + e0 + tx*4 + j] = acc[i][j] + bias[j];
}

// ---------------------------------------------------------------------------
extern "C" void kernel_launch(void* const* d_in, const int* in_sizes, int n_in,
                              void* d_out, int out_size)
{
    const float* x    = (const float*)d_in[0];
    const float* mask = (const float*)d_in[1];
    const float* Wq   = (const float*)d_in[2];
    const float* bq   = (const float*)d_in[3];
    const float* Wk   = (const float*)d_in[4];
    const float* bk   = (const float*)d_in[5];
    const float* Wv   = (const float*)d_in[6];
    const float* bv   = (const float*)d_in[7];
    const float* Wo   = (const float*)d_in[8];
    const float* bo   = (const float*)d_in[9];
    float* out = (float*)d_out;

    // >48KB dynamic smem opt-in (idempotent, capture-safe)
    cudaFuncSetAttribute(attn_kernel, cudaFuncAttributeMaxDynamicSharedMemorySize, ATTN_SMEM);

    qkv_kernel<<<dim3(BH, SS/64), 256>>>(x, Wq, bq, Wk, bk, Wv, bv);
    attn_kernel<<<dim3(BH, SS/64), 256, ATTN_SMEM>>>(mask);
    out_kernel<<<dim3(EE/64, (BB*SS)/64), 256>>>(Wo, bo, out);
}

// round 4
// speedup vs baseline: 1.3133x; 1.3133x over previous
#include <cuda_runtime.h>
#include <math.h>
#include <cstdint>

// Problem constants
#define BB 2
#define SS 2048
#define EE 1024
#define HH 16
#define HD 64
#define BH (BB*HH)
#define SCALE 0.125f   // 1/sqrt(64)
#define TS 68          // padded stride for SIMT smem tiles

// strides for mma smem tiles (conflict-free for fragment access patterns)
#define BST 72   // B-operand tiles (row-major k x n)
#define AST 68   // A-operand / P tiles (row-major m x k)

// Scratch (allocation-free rule: __device__ globals)
static __device__ float g_q [(size_t)BH*SS*64];       // (bh, s, d)
static __device__ float g_kt[(size_t)BH*64*SS];       // (bh, d, s)  K transposed
static __device__ float g_v [(size_t)BH*SS*64];       // (bh, s, d)
static __device__ float g_att[(size_t)BB*SS*EE];      // (b, s, h*64)

// ---------------------------------------------------------------------------
// tf32 helpers
// ---------------------------------------------------------------------------
__device__ __forceinline__ uint32_t f2tf32(float x) {
    uint32_t r;
    asm("cvt.rna.tf32.f32 %0, %1;" : "=r"(r) : "f"(x));
    return r;
}
__device__ __forceinline__ void split_tf32(float x, uint32_t& hi, uint32_t& lo) {
    hi = f2tf32(x);
    lo = f2tf32(x - __uint_as_float(hi));
}
// D(16x8) += A(16x8) * B(8x8)
__device__ __forceinline__ void mma_tf32(float c[4], uint32_t a0, uint32_t a1,
                                         uint32_t a2, uint32_t a3,
                                         uint32_t b0, uint32_t b1) {
    asm volatile(
        "mma.sync.aligned.m16n8k8.row.col.f32.tf32.tf32.f32 "
        "{%0,%1,%2,%3}, {%4,%5,%6,%7}, {%8,%9}, {%0,%1,%2,%3};"
        : "+f"(c[0]), "+f"(c[1]), "+f"(c[2]), "+f"(c[3])
        : "r"(a0), "r"(a1), "r"(a2), "r"(a3), "r"(b0), "r"(b1));
}

// ---------------------------------------------------------------------------
// Kernel 1: per-head QKV projection (SIMT fp32, exact).
// Emits Q (s,d), K transposed (d,s), V (s,d).
// ---------------------------------------------------------------------------
__global__ __launch_bounds__(256) void qkv_kernel(
    const float* __restrict__ x,
    const float* __restrict__ Wq, const float* __restrict__ bq,
    const float* __restrict__ Wk, const float* __restrict__ bk,
    const float* __restrict__ Wv, const float* __restrict__ bv)
{
    __shared__ __align__(16) float xT[64*TS];
    __shared__ __align__(16) float Ws[64*64];

    int bh = blockIdx.x; int b = bh >> 4, h = bh & 15;
    int s0 = blockIdx.y * 64;
    int tid = threadIdx.x;
    int tx = tid & 15, ty = tid >> 4;

    for (int idx = tid; idx < 4096; idx += 256) {
        int r = idx >> 6, d = idx & 63;
        xT[d*TS + r] = x[((size_t)b*SS + s0 + r)*EE + h*HD + d];
    }

    const float* Wp[3] = {Wq, Wk, Wv};
    const float* bp[3] = {bq, bk, bv};

    for (int w = 0; w < 3; ++w) {
        __syncthreads();
        for (int idx = tid; idx < 4096; idx += 256) Ws[idx] = Wp[w][idx];
        __syncthreads();

        float acc[4][4] = {};
        #pragma unroll 8
        for (int dd = 0; dd < 64; ++dd) {
            float4 a4 = *(const float4*)&xT[dd*TS + ty*4];
            float4 w4 = *(const float4*)&Ws[dd*64 + tx*4];
            float av[4] = {a4.x, a4.y, a4.z, a4.w};
            float wv[4] = {w4.x, w4.y, w4.z, w4.w};
            #pragma unroll
            for (int i = 0; i < 4; ++i)
                #pragma unroll
                for (int j = 0; j < 4; ++j)
                    acc[i][j] += av[i] * wv[j];
        }

        float bias[4];
        #pragma unroll
        for (int j = 0; j < 4; ++j) bias[j] = bp[w][tx*4 + j];

        if (w == 0) {
            #pragma unroll
            for (int i = 0; i < 4; ++i)
                #pragma unroll
                for (int j = 0; j < 4; ++j)
                    g_q[((size_t)bh*SS + s0 + ty*4 + i)*64 + tx*4 + j] = acc[i][j] + bias[j];
        } else if (w == 1) {
            #pragma unroll
            for (int i = 0; i < 4; ++i)
                #pragma unroll
                for (int j = 0; j < 4; ++j)
                    g_kt[((size_t)bh*64 + tx*4 + j)*SS + s0 + ty*4 + i] = acc[i][j] + bias[j];
        } else {
            #pragma unroll
            for (int i = 0; i < 4; ++i)
                #pragma unroll
                for (int j = 0; j < 4; ++j)
                    g_v[((size_t)bh*SS + s0 + ty*4 + i)*64 + tx*4 + j] = acc[i][j] + bias[j];
        }
    }
}

// ---------------------------------------------------------------------------
// Kernel 2: attention on tf32 mma.sync.
// CTA = (bh, 128 q-rows), 256 threads = 8 warps x 16 q-rows.
// QK: plain tf32 (error damped by SCALE*mask before exp).
// PV: 3xTF32 compensated (hi/lo split from fp32 smem on the fly).
// No-max softmax; O accumulated across all tiles; one divide at the end.
// ---------------------------------------------------------------------------
#define ATTN_SMEM_FLOATS (2*64*BST + 8*16*AST)
#define ATTN_SMEM_BYTES  (ATTN_SMEM_FLOATS*4)

__global__ __launch_bounds__(256) void attn_mma_kernel(const float* __restrict__ mask)
{
    extern __shared__ __align__(16) float smf[];
    float* kT = smf;                   // [d][s] stride BST
    float* Vs = smf + 64*BST;          // [s][v] stride BST
    float* Pb = smf + 2*64*BST + (threadIdx.x >> 5)*(16*AST);  // per-warp [r][c]

    int tid = threadIdx.x;
    int lane = tid & 31;
    int warp = tid >> 5;
    int g = lane >> 2, q = lane & 3;

    int bh = blockIdx.x, b = bh >> 4, h = bh & 15;
    int q0 = blockIdx.y * 128;
    int wr = q0 + warp * 16;

    // Q fragments (SCALE folded, rna-rounded to tf32)
    uint32_t aq[8][4];
    {
        const float* qb = &g_q[((size_t)bh*SS + wr)*64];
        #pragma unroll
        for (int kk = 0; kk < 8; ++kk) {
            aq[kk][0] = f2tf32(qb[(size_t)g      *64 + kk*8 + q    ] * SCALE);
            aq[kk][1] = f2tf32(qb[(size_t)(g + 8)*64 + kk*8 + q    ] * SCALE);
            aq[kk][2] = f2tf32(qb[(size_t)g      *64 + kk*8 + q + 4] * SCALE);
            aq[kk][3] = f2tf32(qb[(size_t)(g + 8)*64 + kk*8 + q + 4] * SCALE);
        }
    }

    float oacc[8][4] = {};
    float lsum0 = 0.f, lsum1 = 0.f;

    for (int jt = 0; jt < SS/64; ++jt) {
        int s0 = jt * 64;
        __syncthreads();

        for (int idx = tid; idx < 1024; idx += 256) {
            int row = idx >> 4, c4 = (idx & 15) * 4;
            *(float4*)&kT[row*BST + c4] = *(const float4*)&g_kt[((size_t)bh*64 + row)*SS + s0 + c4];
            *(float4*)&Vs[row*BST + c4] = *(const float4*)&g_v [((size_t)bh*SS + s0 + row)*64 + c4];
        }
        for (int i = lane; i < 256; i += 32) {
            int r = i >> 4, c4 = (i & 15) * 4;
            *(float4*)&Pb[r*AST + c4] = *(const float4*)&mask[(size_t)(wr + r)*SS + s0 + c4];
        }
        __syncthreads();

        // S = Q K^T (scaled)
        float sacc[8][4] = {};
        #pragma unroll
        for (int kk = 0; kk < 8; ++kk) {
            #pragma unroll
            for (int nb = 0; nb < 8; ++nb) {
                uint32_t b0 = f2tf32(kT[(kk*8 + q    )*BST + nb*8 + g]);
                uint32_t b1 = f2tf32(kT[(kk*8 + q + 4)*BST + nb*8 + g]);
                mma_tf32(sacc[nb], aq[kk][0], aq[kk][1], aq[kk][2], aq[kk][3], b0, b1);
            }
        }

        // P = exp(S * mask), row partial sums; write P (fp32) into Pb in place
        float ps0 = 0.f, ps1 = 0.f;
        #pragma unroll
        for (int nb = 0; nb < 8; ++nb) {
            int c = nb*8 + 2*q;
            float m0 = Pb[g*AST + c], m1 = Pb[g*AST + c + 1];
            float m2 = Pb[(g + 8)*AST + c], m3 = Pb[(g + 8)*AST + c + 1];
            float p0 = __expf(sacc[nb][0] * m0);
            float p1 = __expf(sacc[nb][1] * m1);
            float p2 = __expf(sacc[nb][2] * m2);
            float p3 = __expf(sacc[nb][3] * m3);
            ps0 += p0 + p1; ps1 += p2 + p3;
            Pb[g*AST + c] = p0;       Pb[g*AST + c + 1] = p1;
            Pb[(g + 8)*AST + c] = p2; Pb[(g + 8)*AST + c + 1] = p3;
        }
        __syncwarp();
        ps0 += __shfl_xor_sync(0xffffffffu, ps0, 1);
        ps0 += __shfl_xor_sync(0xffffffffu, ps0, 2);
        ps1 += __shfl_xor_sync(0xffffffffu, ps1, 1);
        ps1 += __shfl_xor_sync(0xffffffffu, ps1, 2);
        lsum0 += ps0; lsum1 += ps1;

        // O += P V   (3xTF32: ah*bh + ah*bl + al*bh)
        #pragma unroll
        for (int kk = 0; kk < 8; ++kk) {
            uint32_t ah[4], al[4];
            split_tf32(Pb[g*AST       + kk*8 + q    ], ah[0], al[0]);
            split_tf32(Pb[(g + 8)*AST + kk*8 + q    ], ah[1], al[1]);
            split_tf32(Pb[g*AST       + kk*8 + q + 4], ah[2], al[2]);
            split_tf32(Pb[(g + 8)*AST + kk*8 + q + 4], ah[3], al[3]);
            #pragma unroll
            for (int nb = 0; nb < 8; ++nb) {
                uint32_t bh0, bl0, bh1, bl1;
                split_tf32(Vs[(kk*8 + q    )*BST + nb*8 + g], bh0, bl0);
                split_tf32(Vs[(kk*8 + q + 4)*BST + nb*8 + g], bh1, bl1);
                mma_tf32(oacc[nb], ah[0], ah[1], ah[2], ah[3], bh0, bh1);
                mma_tf32(oacc[nb], ah[0], ah[1], ah[2], ah[3], bl0, bl1);
                mma_tf32(oacc[nb], al[0], al[1], al[2], al[3], bh0, bh1);
            }
        }
    }

    float inv0 = 1.f / lsum0, inv1 = 1.f / lsum1;
    float* o0 = &g_att[((size_t)b*SS + wr + g    )*EE + h*64];
    float* o1 = &g_att[((size_t)b*SS + wr + g + 8)*EE + h*64];
    #pragma unroll
    for (int nb = 0; nb < 8; ++nb) {
        int c = nb*8 + 2*q;
        o0[c]     = oacc[nb][0] * inv0;
        o0[c + 1] = oacc[nb][1] * inv0;
        o1[c]     = oacc[nb][2] * inv1;
        o1[c + 1] = oacc[nb][3] * inv1;
    }
}

// ---------------------------------------------------------------------------
// Kernel 3: output projection, 3xTF32.
// out(4096x1024) = g_att @ Wo + bo.  CTA tile 128x64, K chunks of 64.
// ---------------------------------------------------------------------------
#define OUT_SMEM_FLOATS (128*AST + 64*BST)
#define OUT_SMEM_BYTES  (OUT_SMEM_FLOATS*4)

__global__ __launch_bounds__(256) void out_mma_kernel(
    const float* __restrict__ Wo, const float* __restrict__ bo,
    float* __restrict__ out)
{
    extern __shared__ __align__(16) float smf[];
    float* At = smf;               // [m=128][k=64] stride AST
    float* Bs = smf + 128*AST;     // [k=64][n=64] stride BST

    int tid = threadIdx.x;
    int lane = tid & 31;
    int warp = tid >> 5;
    int g = lane >> 2, q = lane & 3;

    int e0 = blockIdx.x * 64;
    int r0 = blockIdx.y * 128;
    int wm = warp * 16;

    float oacc[8][4] = {};

    for (int kc = 0; kc < EE; kc += 64) {
        __syncthreads();
        for (int idx = tid; idx < 2048; idx += 256) {
            int row = idx >> 4, c4 = (idx & 15) * 4;
            *(float4*)&At[row*AST + c4] = *(const float4*)&g_att[(size_t)(r0 + row)*EE + kc + c4];
        }
        for (int idx = tid; idx < 1024; idx += 256) {
            int row = idx >> 4, c4 = (idx & 15) * 4;
            *(float4*)&Bs[row*BST + c4] = *(const float4*)&Wo[(size_t)(kc + row)*EE + e0 + c4];
        }
        __syncthreads();

        #pragma unroll
        for (int kk = 0; kk < 8; ++kk) {
            uint32_t ah[4], al[4];
            split_tf32(At[(wm + g    )*AST + kk*8 + q    ], ah[0], al[0]);
            split_tf32(At[(wm + g + 8)*AST + kk*8 + q    ], ah[1], al[1]);
            split_tf32(At[(wm + g    )*AST + kk*8 + q + 4], ah[2], al[2]);
            split_tf32(At[(wm + g + 8)*AST + kk*8 + q + 4], ah[3], al[3]);
            #pragma unroll
            for (int nb = 0; nb < 8; ++nb) {
                uint32_t bh0, bl0, bh1, bl1;
                split_tf32(Bs[(kk*8 + q    )*BST + nb*8 + g], bh0, bl0);
                split_tf32(Bs[(kk*8 + q + 4)*BST + nb*8 + g], bh1, bl1);
                mma_tf32(oacc[nb], ah[0], ah[1], ah[2], ah[3], bh0, bh1);
                mma_tf32(oacc[nb], ah[0], ah[1], ah[2], ah[3], bl0, bl1);
                mma_tf32(oacc[nb], al[0], al[1], al[2], al[3], bh0, bh1);
            }
        }
    }

    float* o0 = &out[(size_t)(r0 + wm + g    )*EE + e0];
    float* o1 = &out[(size_t)(r0 + wm + g + 8)*EE + e0];
    #pragma unroll
    for (int nb = 0; nb < 8; ++nb) {
        int c = nb*8 + 2*q;
        float bb0 = bo[e0 + c], bb1 = bo[e0 + c + 1];
        o0[c]     = oacc[nb][0] + bb0;
        o0[c + 1] = oacc[nb][1] + bb1;
        o1[c]     = oacc[nb][2] + bb0;
        o1[c + 1] = oacc[nb][3] + bb1;
    }
}

// ---------------------------------------------------------------------------
extern "C" void kernel_launch(void* const* d_in, const int* in_sizes, int n_in,
                              void* d_out, int out_size)
{
    const float* x    = (const float*)d_in[0];
    const float* mask = (const float*)d_in[1];
    const float* Wq   = (const float*)d_in[2];
    const float* bq   = (const float*)d_in[3];
    const float* Wk   = (const float*)d_in[4];
    const float* bk   = (const float*)d_in[5];
    const float* Wv   = (const float*)d_in[6];
    const float* bv   = (const float*)d_in[7];
    const float* Wo   = (const float*)d_in[8];
    const float* bo   = (const float*)d_in[9];
    float* out = (float*)d_out;

    cudaFuncSetAttribute(attn_mma_kernel, cudaFuncAttributeMaxDynamicSharedMemorySize, ATTN_SMEM_BYTES);
    cudaFuncSetAttribute(out_mma_kernel,  cudaFuncAttributeMaxDynamicSharedMemorySize, OUT_SMEM_BYTES);

    qkv_kernel<<<dim3(BH, SS/64), 256>>>(x, Wq, bq, Wk, bk, Wv, bv);
    attn_mma_kernel<<<dim3(BH, SS/128), 256, ATTN_SMEM_BYTES>>>(mask);
    out_mma_kernel<<<dim3(EE/64, (BB*SS)/128), 256, OUT_SMEM_BYTES>>>(Wo, bo, out);
}

// round 5
// speedup vs baseline: 2.2938x; 1.7467x over previous
#include <cuda_runtime.h>
#include <math.h>
#include <cstdint>

// Problem constants
#define BB 2
#define SS 2048
#define EE 1024
#define HH 16
#define HD 64
#define BH (BB*HH)
#define SCALE 0.125f   // 1/sqrt(64)

// strides for mma smem tiles (conflict-free for fragment access patterns)
#define BST 72   // B-operand tiles (row-major k x n)
#define AST 68   // A-operand / P tiles (row-major m x k)

// Scratch (allocation-free rule: __device__ globals)
static __device__ float g_q [(size_t)BH*SS*64];       // (bh, s, d)
static __device__ float g_kt[(size_t)BH*64*SS];       // (bh, d, s)  K transposed
static __device__ float g_v [(size_t)BH*SS*64];       // (bh, s, d)
static __device__ float g_att[(size_t)BB*SS*EE];      // (b, s, h*64)

// ---------------------------------------------------------------------------
// tf32 helpers
// ---------------------------------------------------------------------------
__device__ __forceinline__ uint32_t f2tf32(float x) {
    uint32_t r;
    asm("cvt.rna.tf32.f32 %0, %1;" : "=r"(r) : "f"(x));
    return r;
}
__device__ __forceinline__ void split_tf32(float x, uint32_t& hi, uint32_t& lo) {
    hi = f2tf32(x);
    lo = f2tf32(x - __uint_as_float(hi));
}
// D(16x8) += A(16x8) * B(8x8)
__device__ __forceinline__ void mma_tf32(float c[4], uint32_t a0, uint32_t a1,
                                         uint32_t a2, uint32_t a3,
                                         uint32_t b0, uint32_t b1) {
    asm volatile(
        "mma.sync.aligned.m16n8k8.row.col.f32.tf32.tf32.f32 "
        "{%0,%1,%2,%3}, {%4,%5,%6,%7}, {%8,%9}, {%0,%1,%2,%3};"
        : "+f"(c[0]), "+f"(c[1]), "+f"(c[2]), "+f"(c[3])
        : "r"(a0), "r"(a1), "r"(a2), "r"(a3), "r"(b0), "r"(b1));
}

// ---------------------------------------------------------------------------
// Kernel 1: QKV projection on tf32 mma.
// CTA = (bh, 128-row s tile), 256 threads = 8 warps x 16 rows.
// All three W matrices resident in smem; x tile loaded once.
// Emits Q (s,d), K transposed (d,s), V (s,d).  (tf32 input rounding on x/W is
// damped downstream: q,k feed scaled logits, v passes linearly ~1e-4.)
// ---------------------------------------------------------------------------
#define QKV_SMEM_FLOATS (128*AST + 3*64*BST)
#define QKV_SMEM_BYTES  (QKV_SMEM_FLOATS*4)

__global__ __launch_bounds__(256) void qkv_mma_kernel(
    const float* __restrict__ x,
    const float* __restrict__ Wq, const float* __restrict__ bq,
    const float* __restrict__ Wk, const float* __restrict__ bk,
    const float* __restrict__ Wv, const float* __restrict__ bv)
{
    extern __shared__ __align__(16) float smf[];
    float* At = smf;                 // [m=128][k=64] stride AST
    float* Ws = smf + 128*AST;       // 3 x [k=64][n=64] stride BST

    int tid  = threadIdx.x;
    int lane = tid & 31;
    int warp = tid >> 5;
    int g = lane >> 2, q = lane & 3;

    int bh = blockIdx.x; int b = bh >> 4, h = bh & 15;
    int s0 = blockIdx.y * 128;
    int wm = warp * 16;

    for (int idx = tid; idx < 2048; idx += 256) {          // x tile: 128 x 16 float4
        int row = idx >> 4, c4 = (idx & 15) * 4;
        *(float4*)&At[row*AST + c4] = *(const float4*)&x[((size_t)b*SS + s0 + row)*EE + h*HD + c4];
    }
    const float* Wp[3] = {Wq, Wk, Wv};
    for (int w = 0; w < 3; ++w)
        for (int idx = tid; idx < 1024; idx += 256) {      // W: 64 x 16 float4
            int row = idx >> 4, c4 = (idx & 15) * 4;
            *(float4*)&Ws[w*64*BST + row*BST + c4] = *(const float4*)&Wp[w][(size_t)row*64 + c4];
        }
    __syncthreads();

    const float* bp[3] = {bq, bk, bv};
    for (int w = 0; w < 3; ++w) {
        float acc[8][4] = {};
        const float* B = &Ws[w*64*BST];
        #pragma unroll
        for (int kk = 0; kk < 8; ++kk) {
            uint32_t a0 = f2tf32(At[(wm + g    )*AST + kk*8 + q    ]);
            uint32_t a1 = f2tf32(At[(wm + g + 8)*AST + kk*8 + q    ]);
            uint32_t a2 = f2tf32(At[(wm + g    )*AST + kk*8 + q + 4]);
            uint32_t a3 = f2tf32(At[(wm + g + 8)*AST + kk*8 + q + 4]);
            #pragma unroll
            for (int nb = 0; nb < 8; ++nb) {
                uint32_t b0 = f2tf32(B[(kk*8 + q    )*BST + nb*8 + g]);
                uint32_t b1 = f2tf32(B[(kk*8 + q + 4)*BST + nb*8 + g]);
                mma_tf32(acc[nb], a0, a1, a2, a3, b0, b1);
            }
        }

        int r0g = s0 + wm + g, r1g = s0 + wm + g + 8;
        #pragma unroll
        for (int nb = 0; nb < 8; ++nb) {
            int c = nb*8 + 2*q;
            float bb0 = bp[w][c], bb1 = bp[w][c + 1];
            float v00 = acc[nb][0] + bb0, v01 = acc[nb][1] + bb1;
            float v10 = acc[nb][2] + bb0, v11 = acc[nb][3] + bb1;
            if (w == 0) {
                float* o = &g_q[((size_t)bh*SS)*64];
                o[(size_t)r0g*64 + c] = v00; o[(size_t)r0g*64 + c + 1] = v01;
                o[(size_t)r1g*64 + c] = v10; o[(size_t)r1g*64 + c + 1] = v11;
            } else if (w == 1) {
                float* o = &g_kt[(size_t)bh*64*SS];
                o[(size_t)c*SS + r0g]       = v00; o[(size_t)(c + 1)*SS + r0g] = v01;
                o[(size_t)c*SS + r1g]       = v10; o[(size_t)(c + 1)*SS + r1g] = v11;
            } else {
                float* o = &g_v[((size_t)bh*SS)*64];
                o[(size_t)r0g*64 + c] = v00; o[(size_t)r0g*64 + c + 1] = v01;
                o[(size_t)r1g*64 + c] = v10; o[(size_t)r1g*64 + c + 1] = v11;
            }
        }
    }
}

// ---------------------------------------------------------------------------
// Kernel 2: attention on tf32 mma.
// CTA = (bh, 128 q-rows), 256 threads = 8 warps x 16 q-rows.
// QK: 1x tf32 (error damped by SCALE*mask before exp).
// PV: 2x — P stored rna-rounded in smem (raw LDS A-frags), V pre-split
//     cooperatively into Vh/Vl smem tiles.
// No-max softmax; O accumulated across all 32 tiles; one divide at the end.
// ---------------------------------------------------------------------------
#define ATTN_SMEM_FLOATS (3*64*BST + 8*16*AST)
#define ATTN_SMEM_BYTES  (ATTN_SMEM_FLOATS*4)

__global__ __launch_bounds__(256) void attn_mma_kernel(const float* __restrict__ mask)
{
    extern __shared__ __align__(16) float smf[];
    float* kT = smf;                   // [d][s] stride BST
    float* Vh = smf + 64*BST;          // [s][v] hi, stride BST
    float* Vl = smf + 2*64*BST;        // [s][v] lo, stride BST
    float* Pb = smf + 3*64*BST + (threadIdx.x >> 5)*(16*AST);  // per-warp [r][c]

    int tid = threadIdx.x;
    int lane = tid & 31;
    int warp = tid >> 5;
    int g = lane >> 2, q = lane & 3;

    int bh = blockIdx.x, b = bh >> 4, h = bh & 15;
    int q0 = blockIdx.y * 128;
    int wr = q0 + warp * 16;

    // Q fragments (SCALE folded, rna-rounded), kept for all 32 KV tiles
    uint32_t aq[8][4];
    {
        const float* qb = &g_q[((size_t)bh*SS + wr)*64];
        #pragma unroll
        for (int kk = 0; kk < 8; ++kk) {
            aq[kk][0] = f2tf32(qb[(size_t)g      *64 + kk*8 + q    ] * SCALE);
            aq[kk][1] = f2tf32(qb[(size_t)(g + 8)*64 + kk*8 + q    ] * SCALE);
            aq[kk][2] = f2tf32(qb[(size_t)g      *64 + kk*8 + q + 4] * SCALE);
            aq[kk][3] = f2tf32(qb[(size_t)(g + 8)*64 + kk*8 + q + 4] * SCALE);
        }
    }

    float oacc[8][4] = {};
    float lsum0 = 0.f, lsum1 = 0.f;

    for (int jt = 0; jt < SS/64; ++jt) {
        int s0 = jt * 64;
        __syncthreads();

        for (int idx = tid; idx < 1024; idx += 256) {
            int row = idx >> 4, c4 = (idx & 15) * 4;
            *(float4*)&kT[row*BST + c4] = *(const float4*)&g_kt[((size_t)bh*64 + row)*SS + s0 + c4];
            float4 v = *(const float4*)&g_v[((size_t)bh*SS + s0 + row)*64 + c4];
            float4 vh, vl; uint32_t h32, l32;
            split_tf32(v.x, h32, l32); vh.x = __uint_as_float(h32); vl.x = __uint_as_float(l32);
            split_tf32(v.y, h32, l32); vh.y = __uint_as_float(h32); vl.y = __uint_as_float(l32);
            split_tf32(v.z, h32, l32); vh.z = __uint_as_float(h32); vl.z = __uint_as_float(l32);
            split_tf32(v.w, h32, l32); vh.w = __uint_as_float(h32); vl.w = __uint_as_float(l32);
            *(float4*)&Vh[row*BST + c4] = vh;
            *(float4*)&Vl[row*BST + c4] = vl;
        }
        for (int i = lane; i < 256; i += 32) {
            int r = i >> 4, c4 = (i & 15) * 4;
            *(float4*)&Pb[r*AST + c4] = *(const float4*)&mask[(size_t)(wr + r)*SS + s0 + c4];
        }
        __syncthreads();

        // S = Q K^T (scaled)
        float sacc[8][4] = {};
        #pragma unroll
        for (int kk = 0; kk < 8; ++kk) {
            #pragma unroll
            for (int nb = 0; nb < 8; ++nb) {
                uint32_t b0 = f2tf32(kT[(kk*8 + q    )*BST + nb*8 + g]);
                uint32_t b1 = f2tf32(kT[(kk*8 + q + 4)*BST + nb*8 + g]);
                mma_tf32(sacc[nb], aq[kk][0], aq[kk][1], aq[kk][2], aq[kk][3], b0, b1);
            }
        }

        // P = exp(S * mask), rna-rounded into Pb in place; row partial sums
        float ps0 = 0.f, ps1 = 0.f;
        #pragma unroll
        for (int nb = 0; nb < 8; ++nb) {
            int c = nb*8 + 2*q;
            float m0 = Pb[g*AST + c], m1 = Pb[g*AST + c + 1];
            float m2 = Pb[(g + 8)*AST + c], m3 = Pb[(g + 8)*AST + c + 1];
            float p0 = __uint_as_float(f2tf32(__expf(sacc[nb][0] * m0)));
            float p1 = __uint_as_float(f2tf32(__expf(sacc[nb][1] * m1)));
            float p2 = __uint_as_float(f2tf32(__expf(sacc[nb][2] * m2)));
            float p3 = __uint_as_float(f2tf32(__expf(sacc[nb][3] * m3)));
            ps0 += p0 + p1; ps1 += p2 + p3;
            Pb[g*AST + c] = p0;       Pb[g*AST + c + 1] = p1;
            Pb[(g + 8)*AST + c] = p2; Pb[(g + 8)*AST + c + 1] = p3;
        }
        ps0 += __shfl_xor_sync(0xffffffffu, ps0, 1);
        ps0 += __shfl_xor_sync(0xffffffffu, ps0, 2);
        ps1 += __shfl_xor_sync(0xffffffffu, ps1, 1);
        ps1 += __shfl_xor_sync(0xffffffffu, ps1, 2);
        lsum0 += ps0; lsum1 += ps1;
        __syncwarp();

        // O += P V   (2x: P * Vh + P * Vl; P already tf32 in smem)
        #pragma unroll
        for (int kk = 0; kk < 8; ++kk) {
            uint32_t a0 = __float_as_uint(Pb[g*AST       + kk*8 + q    ]);
            uint32_t a1 = __float_as_uint(Pb[(g + 8)*AST + kk*8 + q    ]);
            uint32_t a2 = __float_as_uint(Pb[g*AST       + kk*8 + q + 4]);
            uint32_t a3 = __float_as_uint(Pb[(g + 8)*AST + kk*8 + q + 4]);
            #pragma unroll
            for (int nb = 0; nb < 8; ++nb) {
                uint32_t bh0 = __float_as_uint(Vh[(kk*8 + q    )*BST + nb*8 + g]);
                uint32_t bh1 = __float_as_uint(Vh[(kk*8 + q + 4)*BST + nb*8 + g]);
                uint32_t bl0 = __float_as_uint(Vl[(kk*8 + q    )*BST + nb*8 + g]);
                uint32_t bl1 = __float_as_uint(Vl[(kk*8 + q + 4)*BST + nb*8 + g]);
                mma_tf32(oacc[nb], a0, a1, a2, a3, bh0, bh1);
                mma_tf32(oacc[nb], a0, a1, a2, a3, bl0, bl1);
            }
        }
    }

    float inv0 = 1.f / lsum0, inv1 = 1.f / lsum1;
    float* o0 = &g_att[((size_t)b*SS + wr + g    )*EE + h*64];
    float* o1 = &g_att[((size_t)b*SS + wr + g + 8)*EE + h*64];
    #pragma unroll
    for (int nb = 0; nb < 8; ++nb) {
        int c = nb*8 + 2*q;
        o0[c]     = oacc[nb][0] * inv0;
        o0[c + 1] = oacc[nb][1] * inv0;
        o1[c]     = oacc[nb][2] * inv1;
        o1[c + 1] = oacc[nb][3] * inv1;
    }
}

// ---------------------------------------------------------------------------
// Kernel 3: output projection, 2x tf32 (A split, B rna).
// out(4096x1024) = g_att @ Wo + bo.  CTA tile 128x64, K chunks of 64.
// ---------------------------------------------------------------------------
#define OUT_SMEM_FLOATS (128*AST + 64*BST)
#define OUT_SMEM_BYTES  (OUT_SMEM_FLOATS*4)

__global__ __launch_bounds__(256) void out_mma_kernel(
    const float* __restrict__ Wo, const float* __restrict__ bo,
    float* __restrict__ out)
{
    extern __shared__ __align__(16) float smf[];
    float* At = smf;               // [m=128][k=64] stride AST
    float* Bs = smf + 128*AST;     // [k=64][n=64] stride BST

    int tid = threadIdx.x;
    int lane = tid & 31;
    int warp = tid >> 5;
    int g = lane >> 2, q = lane & 3;

    int e0 = blockIdx.x * 64;
    int r0 = blockIdx.y * 128;
    int wm = warp * 16;

    float oacc[8][4] = {};

    for (int kc = 0; kc < EE; kc += 64) {
        __syncthreads();
        for (int idx = tid; idx < 2048; idx += 256) {
            int row = idx >> 4, c4 = (idx & 15) * 4;
            *(float4*)&At[row*AST + c4] = *(const float4*)&g_att[(size_t)(r0 + row)*EE + kc + c4];
        }
        for (int idx = tid; idx < 1024; idx += 256) {
            int row = idx >> 4, c4 = (idx & 15) * 4;
            *(float4*)&Bs[row*BST + c4] = *(const float4*)&Wo[(size_t)(kc + row)*EE + e0 + c4];
        }
        __syncthreads();

        #pragma unroll
        for (int kk = 0; kk < 8; ++kk) {
            uint32_t ah[4], al[4];
            split_tf32(At[(wm + g    )*AST + kk*8 + q    ], ah[0], al[0]);
            split_tf32(At[(wm + g + 8)*AST + kk*8 + q    ], ah[1], al[1]);
            split_tf32(At[(wm + g    )*AST + kk*8 + q + 4], ah[2], al[2]);
            split_tf32(At[(wm + g + 8)*AST + kk*8 + q + 4], ah[3], al[3]);
            #pragma unroll
            for (int nb = 0; nb < 8; ++nb) {
                uint32_t b0 = f2tf32(Bs[(kk*8 + q    )*BST + nb*8 + g]);
                uint32_t b1 = f2tf32(Bs[(kk*8 + q + 4)*BST + nb*8 + g]);
                mma_tf32(oacc[nb], ah[0], ah[1], ah[2], ah[3], b0, b1);
                mma_tf32(oacc[nb], al[0], al[1], al[2], al[3], b0, b1);
            }
        }
    }

    float* o0 = &out[(size_t)(r0 + wm + g    )*EE + e0];
    float* o1 = &out[(size_t)(r0 + wm + g + 8)*EE + e0];
    #pragma unroll
    for (int nb = 0; nb < 8; ++nb) {
        int c = nb*8 + 2*q;
        float bb0 = bo[e0 + c], bb1 = bo[e0 + c + 1];
        o0[c]     = oacc[nb][0] + bb0;
        o0[c + 1] = oacc[nb][1] + bb1;
        o1[c]     = oacc[nb][2] + bb0;
        o1[c + 1] = oacc[nb][3] + bb1;
    }
}

// ---------------------------------------------------------------------------
extern "C" void kernel_launch(void* const* d_in, const int* in_sizes, int n_in,
                              void* d_out, int out_size)
{
    const float* x    = (const float*)d_in[0];
    const float* mask = (const float*)d_in[1];
    const float* Wq   = (const float*)d_in[2];
    const float* bq   = (const float*)d_in[3];
    const float* Wk   = (const float*)d_in[4];
    const float* bk   = (const float*)d_in[5];
    const float* Wv   = (const float*)d_in[6];
    const float* bv   = (const float*)d_in[7];
    const float* Wo   = (const float*)d_in[8];
    const float* bo   = (const float*)d_in[9];
    float* out = (float*)d_out;

    cudaFuncSetAttribute(qkv_mma_kernel,  cudaFuncAttributeMaxDynamicSharedMemorySize, QKV_SMEM_BYTES);
    cudaFuncSetAttribute(attn_mma_kernel, cudaFuncAttributeMaxDynamicSharedMemorySize, ATTN_SMEM_BYTES);
    cudaFuncSetAttribute(out_mma_kernel,  cudaFuncAttributeMaxDynamicSharedMemorySize, OUT_SMEM_BYTES);

    qkv_mma_kernel<<<dim3(BH, SS/128), 256, QKV_SMEM_BYTES>>>(x, Wq, bq, Wk, bk, Wv, bv);
    attn_mma_kernel<<<dim3(BH, SS/128), 256, ATTN_SMEM_BYTES>>>(mask);
    out_mma_kernel<<<dim3(EE/64, (BB*SS)/128), 256, OUT_SMEM_BYTES>>>(Wo, bo, out);
}